// round 3
// baseline (speedup 1.0000x reference)
#include <cuda_runtime.h>

// x: [16, 64, 256, 256] f32  ->  out: [16, 64, 128, 128] f32
// Per 2x2 window: m = max|v_i|; out = max_i(|v_i|==m ? v_i : 0).
// NC = 1024, H=W=256, OH=OW=128.
// One thread -> 4 output pixels as TWO pixel-pairs 64 input-floats apart:
//   4x LDG.128 (each per-instruction fully coalesced: lanes -> consecutive
//   float4) + 2x STG.64 (coalesced). MLP_p1 = 4.

static __device__ __forceinline__ float win_result(float a, float b, float c, float d) {
    float aa = fabsf(a), ab = fabsf(b), ac = fabsf(c), ad = fabsf(d);
    float m = fmaxf(fmaxf(aa, ab), fmaxf(ac, ad));
    float r = fmaxf(fmaxf(aa == m ? a : 0.0f, ab == m ? b : 0.0f),
                    fmaxf(ac == m ? c : 0.0f, ad == m ? d : 0.0f));
    return r;
}

__global__ __launch_bounds__(256) void maxabspool_kernel(
    const float* __restrict__ x, float* __restrict__ out)
{
    // total threads = NC * OH * (OW/4) = 1024 * 128 * 32 = 4194304
    unsigned idx = blockIdx.x * 256u + threadIdx.x;

    unsigned owh = idx & 31u;            // half-row position, 0..31
    unsigned oh  = (idx >> 5) & 127u;    // 0..127
    unsigned nc  = idx >> 12;            // 0..1023

    // input as float4: plane stride 16384, row stride 64 (256 floats)
    const float4* base = (const float4*)x + (size_t)nc * 16384u + (2u * oh) * 64u;

    // front-batched, each instruction contiguous across the warp
    float4 a0 = base[owh];        // row0, left half
    float4 a1 = base[owh + 32];   // row0, right half
    float4 b0 = base[owh + 64];   // row1, left half
    float4 b1 = base[owh + 96];   // row1, right half

    float2 oL, oR;
    oL.x = win_result(a0.x, a0.y, b0.x, b0.y);
    oL.y = win_result(a0.z, a0.w, b0.z, b0.w);
    oR.x = win_result(a1.x, a1.y, b1.x, b1.y);
    oR.y = win_result(a1.z, a1.w, b1.z, b1.w);

    // output as float2: plane stride 8192, row stride 64 (128 floats)
    float2* dst = (float2*)out + (size_t)nc * 8192u + oh * 64u;
    dst[owh]      = oL;
    dst[owh + 32] = oR;
}

extern "C" void kernel_launch(void* const* d_in, const int* in_sizes, int n_in,
                              void* d_out, int out_size) {
    const float* x = (const float*)d_in[0];
    float* out = (float*)d_out;
    maxabspool_kernel<<<16384, 256>>>(x, out);
}

// round 4
// speedup vs baseline: 1.0210x; 1.0210x over previous
#include <cuda_runtime.h>

// x: [16, 64, 256, 256] f32  ->  out: [16, 64, 128, 128] f32
// Per 2x2 window: m = max|v_i|; out = max_i(|v_i|==m ? v_i : 0).
// NC = 1024, H=W=256, OH=OW=128.
// One thread -> 4 output pixels as TWO pixel-pairs 64 input-floats apart:
//   4x LDG.128 (each per-instruction fully coalesced: lanes -> consecutive
//   float4) + 2x STG.64 (coalesced). MLP_p1 = 4.

static __device__ __forceinline__ float win_result(float a, float b, float c, float d) {
    float aa = fabsf(a), ab = fabsf(b), ac = fabsf(c), ad = fabsf(d);
    float m = fmaxf(fmaxf(aa, ab), fmaxf(ac, ad));
    float r = fmaxf(fmaxf(aa == m ? a : 0.0f, ab == m ? b : 0.0f),
                    fmaxf(ac == m ? c : 0.0f, ad == m ? d : 0.0f));
    return r;
}

__global__ __launch_bounds__(256) void maxabspool_kernel(
    const float* __restrict__ x, float* __restrict__ out)
{
    // total threads = NC * OH * (OW/4) = 1024 * 128 * 32 = 4194304
    unsigned idx = blockIdx.x * 256u + threadIdx.x;

    unsigned owh = idx & 31u;            // half-row position, 0..31
    unsigned oh  = (idx >> 5) & 127u;    // 0..127
    unsigned nc  = idx >> 12;            // 0..1023

    // input as float4: plane stride 16384, row stride 64 (256 floats)
    const float4* base = (const float4*)x + (size_t)nc * 16384u + (2u * oh) * 64u;

    // front-batched, each instruction contiguous across the warp
    float4 a0 = base[owh];        // row0, left half
    float4 a1 = base[owh + 32];   // row0, right half
    float4 b0 = base[owh + 64];   // row1, left half
    float4 b1 = base[owh + 96];   // row1, right half

    float2 oL, oR;
    oL.x = win_result(a0.x, a0.y, b0.x, b0.y);
    oL.y = win_result(a0.z, a0.w, b0.z, b0.w);
    oR.x = win_result(a1.x, a1.y, b1.x, b1.y);
    oR.y = win_result(a1.z, a1.w, b1.z, b1.w);

    // output as float2: plane stride 8192, row stride 64 (128 floats)
    float2* dst = (float2*)out + (size_t)nc * 8192u + oh * 64u;
    dst[owh]      = oL;
    dst[owh + 32] = oR;
}

extern "C" void kernel_launch(void* const* d_in, const int* in_sizes, int n_in,
                              void* d_out, int out_size) {
    const float* x = (const float*)d_in[0];
    float* out = (float*)d_out;
    maxabspool_kernel<<<16384, 256>>>(x, out);
}